// round 7
// baseline (speedup 1.0000x reference)
#include <cuda_runtime.h>
#include <cstdint>
#include <cmath>

#define B_SZ    32768
#define STATE_NN 64
#define HDIM    1024
#define KCODES  256
#define DDIM    128
#define GG      8
#define BG      (B_SZ*GG)      /* 262144 */
#define GD      (GG*DDIM)      /* 1024   */

#define DEC_OFF  1
#define PERP_OFF (1 + B_SZ*STATE_NN)       /* 2097153 */
#define IDX_OFF  (2 + B_SZ*STATE_NN)       /* 2097154 */

typedef unsigned long long u64;

// ---------------- device scratch (no allocations allowed) ----------------
__device__ float g_h1[(size_t)B_SZ*HDIM];
__device__ float g_t2[(size_t)B_SZ*HDIM];
__device__ float g_h2[(size_t)B_SZ*HDIM];
__device__ float g_z [(size_t)B_SZ*GD];
__device__ float g_S [(size_t)BG*KCODES];
__device__ float g_zq[(size_t)B_SZ*GD];
__device__ float g_zn[BG];
__device__ int   g_idx[BG];
__device__ int   g_hist[KCODES];
__device__ float g_cn[KCODES];
__device__ float g_cbT[DDIM*KCODES];
__device__ float g_loss[1];

// ---------------- packed f32x2 helpers ----------------
__device__ __forceinline__ u64 pack2(float lo, float hi){
    u64 r; asm("mov.b64 %0, {%1,%2};" : "=l"(r) : "f"(lo), "f"(hi)); return r;
}
__device__ __forceinline__ void unpack2(u64 v, float &lo, float &hi){
    asm("mov.b64 {%0,%1}, %2;" : "=f"(lo), "=f"(hi) : "l"(v));
}
__device__ __forceinline__ u64 ffma2(u64 a, u64 b, u64 c){
    u64 d; asm("fma.rn.f32x2 %0, %1, %2, %3;" : "=l"(d) : "l"(a), "l"(b), "l"(c)); return d;
}
__device__ __forceinline__ u64 fmul2(u64 a, u64 b){
    u64 d; asm("mul.rn.f32x2 %0, %1, %2;" : "=l"(d) : "l"(a), "l"(b)); return d;
}
__device__ __forceinline__ u64 fadd2(u64 a, u64 b){
    u64 d; asm("add.rn.f32x2 %0, %1, %2;" : "=l"(d) : "l"(a), "l"(b)); return d;
}

// =====================================================================
// fp32 GEMM, FFMA2, row-pair A fragments + duplicated-B smem.
// Per kk: 6 LDS.128, 0 movs, (TM/2)*TN FFMA2.  Bit-identical per-element
// k-accumulation order to the R6 kernel.
// C = act( A[M,K] @ B[K,N] + bias );  ACT: 0 none, 1 relu.  VEC: float4 stores.
// =====================================================================
template<int BM,int BN,int BK,int TM,int TN,int ACT,int VEC>
__global__ void __launch_bounds__(256,2)
gemm2_k(const float* __restrict__ A, const float* __restrict__ Bm,
        const float* __restrict__ bias, float* __restrict__ C,
        int M, int N, int K)
{
    constexpr int MG = TM/4;          // A row groups (2)
    constexpr int NP = TM/2;          // row pairs per thread (4)
    __shared__ float As [BK][BM];     // transposed A tile
    __shared__ u64   Bs2[BK][BN];     // B tile, each elem duplicated (b,b)

    const int tid  = threadIdx.x;
    const int tcol = tid % (BN/TN);
    const int trow = tid / (BN/TN);
    const int aRow0 = blockIdx.y * BM;
    const int bCol0 = blockIdx.x * BN;

    // A-loader mapping: r = tid % BM (conflict-free STS scatter)
    const int lr = tid % BM;
    const int ls = tid / BM;          // 0..(256/BM - 1)

    u64 acc[NP][TN];
#pragma unroll
    for (int i=0;i<NP;i++)
#pragma unroll
        for (int j=0;j<TN;j++) acc[i][j] = 0ULL;

    for (int k0=0; k0<K; k0+=BK) {
        // A tile: thread loads float4 (4 consecutive k) of row lr, scatters
        // to 4 kk-rows.  Bank = lr%32 -> all 32 lanes distinct -> conflict-free.
#pragma unroll
        for (int c0 = ls*4; c0 < BK; c0 += (256/BM)*4) {
            float4 v = *(const float4*)(A + (size_t)(aRow0+lr)*K + k0 + c0);
            As[c0+0][lr]=v.x; As[c0+1][lr]=v.y;
            As[c0+2][lr]=v.z; As[c0+3][lr]=v.w;
        }
        // B tile: duplicated writes, contiguous 32B per lane -> conflict-free.
#pragma unroll
        for (int it=0; it<(BK*BN)/(256*4); ++it) {
            int idx4 = (tid + it*256)*4;
            int r = idx4 / BN, c = idx4 % BN;
            float4 v = *(const float4*)(Bm + (size_t)(k0+r)*N + bCol0 + c);
            ulonglong2 w0, w1;
            w0.x = pack2(v.x,v.x); w0.y = pack2(v.y,v.y);
            w1.x = pack2(v.z,v.z); w1.y = pack2(v.w,v.w);
            *(ulonglong2*)&Bs2[r][c]   = w0;
            *(ulonglong2*)&Bs2[r][c+2] = w1;
        }
        __syncthreads();
#pragma unroll
        for (int kk=0; kk<BK; kk++) {
            u64 ap[NP], bd[TN];
#pragma unroll
            for (int h=0; h<MG; h++) {
                ulonglong2 av = *(const ulonglong2*)&As[kk][h*(BM/2) + trow*4];
                ap[h*2+0] = av.x;     // rows (base,   base+1)
                ap[h*2+1] = av.y;     // rows (base+2, base+3)
            }
#pragma unroll
            for (int g=0; g<TN/4; g++) {
                ulonglong2 b0 = *(const ulonglong2*)&Bs2[kk][g*(BN/2) + tcol*4];
                ulonglong2 b1 = *(const ulonglong2*)&Bs2[kk][g*(BN/2) + tcol*4 + 2];
                bd[g*4+0] = b0.x; bd[g*4+1] = b0.y;
                bd[g*4+2] = b1.x; bd[g*4+3] = b1.y;
            }
#pragma unroll
            for (int i=0;i<NP;i++)
#pragma unroll
                for (int j=0;j<TN;j++)
                    acc[i][j] = ffma2(ap[i], bd[j], acc[i][j]);
        }
        __syncthreads();
    }
    // epilogue: acc[i][j] = ( C[row_lo][col_j], C[row_hi][col_j] )
#pragma unroll
    for (int h=0; h<MG; h++) {
#pragma unroll
        for (int p=0; p<2; p++) {
            size_t rlo = (size_t)aRow0 + h*(BM/2) + trow*4 + 2*p;
            size_t rhi = rlo + 1;
            int i = h*2 + p;
#pragma unroll
            for (int g=0; g<TN/4; g++) {
                int c0 = bCol0 + g*(BN/2) + tcol*4;
                float lo[4], hi[4];
#pragma unroll
                for (int jc=0; jc<4; jc++) {
                    unpack2(acc[i][g*4+jc], lo[jc], hi[jc]);
                    float bb = bias[c0+jc];
                    lo[jc] += bb; hi[jc] += bb;
                    if (ACT == 1) { lo[jc]=fmaxf(lo[jc],0.f); hi[jc]=fmaxf(hi[jc],0.f); }
                }
                if (VEC) {
                    float4 o0; o0.x=lo[0]; o0.y=lo[1]; o0.z=lo[2]; o0.w=lo[3];
                    float4 o1; o1.x=hi[0]; o1.y=hi[1]; o1.z=hi[2]; o1.w=hi[3];
                    *(float4*)(C + rlo*N + c0) = o0;
                    *(float4*)(C + rhi*N + c0) = o1;
                } else {
#pragma unroll
                    for (int jc=0; jc<4; jc++) {
                        C[rlo*N + c0 + jc] = lo[jc];
                        C[rhi*N + c0 + jc] = hi[jc];
                    }
                }
            }
        }
    }
}

// =====================================================================
// VQ-score GEMM (verbatim from R4/R6 passing runs): packed Kahan dot,
// then S = fl( fl(zn[r] + cn[c]) - 2*dot ) on the reference rounding grid.
// =====================================================================
template<int BM,int BN,int BK,int TM,int TN>
__global__ void __launch_bounds__(256,2)
gemm_vq2_k(const float* __restrict__ A, const float* __restrict__ Bm,
           const float* __restrict__ cn, const float* __restrict__ zn,
           float* __restrict__ C, int M, int N, int K)
{
    __shared__ float As[BK][BM];
    __shared__ float Bs[BK][BN];

    const int tid  = threadIdx.x;
    const int tcol = tid % (BN/TN);
    const int trow = tid / (BN/TN);
    const int aRow0 = blockIdx.y * BM;
    const int bCol0 = blockIdx.x * BN;
    const u64 SGN = 0x8000000080000000ULL;

    u64 s[TM][TN/2], e[TM][TN/2];
#pragma unroll
    for (int i=0;i<TM;i++)
#pragma unroll
        for (int j=0;j<TN/2;j++) { s[i][j]=0ULL; e[i][j]=0ULL; }

    for (int k0=0; k0<K; k0+=BK) {
#pragma unroll
        for (int it=0; it<(BM*BK)/(256*4); ++it) {
            int idx4 = (tid + it*256)*4;
            int r = idx4 / BK, c = idx4 % BK;
            float4 v = *(const float4*)(A + (size_t)(aRow0+r)*K + k0 + c);
            As[c+0][r]=v.x; As[c+1][r]=v.y; As[c+2][r]=v.z; As[c+3][r]=v.w;
        }
#pragma unroll
        for (int it=0; it<(BK*BN)/(256*4); ++it) {
            int idx4 = (tid + it*256)*4;
            int r = idx4 / BN, c = idx4 % BN;
            *(float4*)&Bs[r][c] = *(const float4*)(Bm + (size_t)(k0+r)*N + bCol0 + c);
        }
        __syncthreads();
#pragma unroll
        for (int kk=0; kk<BK; kk++) {
            u64 ar2[TM], br2[TN/2];
#pragma unroll
            for (int i=0;i<TM;i++) {
                float a = As[kk][trow*TM+i];
                ar2[i] = pack2(a, a);
            }
            {
                ulonglong2 b2 = *(const ulonglong2*)&Bs[kk][tcol*TN];
                br2[0] = b2.x;
                br2[1] = b2.y;
            }
#pragma unroll
            for (int i=0;i<TM;i++)
#pragma unroll
                for (int j=0;j<TN/2;j++) {
                    u64 x  = fmul2(ar2[i], br2[j]);
                    u64 t  = fadd2(s[i][j], x);
                    u64 c1 = fadd2(fadd2(s[i][j], t ^ SGN), x);  // (s-t)+x
                    e[i][j] = fadd2(e[i][j], c1);
                    s[i][j] = t;
                }
        }
        __syncthreads();
    }
#pragma unroll
    for (int i=0;i<TM;i++) {
        size_t r = (size_t)aRow0 + trow*TM + i;
        float zr = zn[r];
#pragma unroll
        for (int j=0;j<TN/2;j++) {
            int c = bCol0 + tcol*TN + 2*j;
            float s0,s1,e0,e1;
            unpack2(s[i][j], s0, s1);
            unpack2(e[i][j], e0, e1);
            float dot0 = __fadd_rn(s0, e0);
            float dot1 = __fadd_rn(s1, e1);
            float t0 = __fadd_rn(zr, cn[c]);
            float t1 = __fadd_rn(zr, cn[c+1]);
            C[r*N + c]   = __fadd_rn(t0, __fmul_rn(-2.f, dot0));
            C[r*N + c+1] = __fadd_rn(t1, __fmul_rn(-2.f, dot1));
        }
    }
}

// ---------------- LayerNorm + ReLU (row of 1024, 256 threads) ----------------
__global__ void ln_relu_k(const float* __restrict__ X, const float* __restrict__ gam,
                          const float* __restrict__ bet, float* __restrict__ Y)
{
    const int row = blockIdx.x;
    const int t   = threadIdx.x;
    __shared__ float red[8];
    __shared__ float s_mu, s_rs;

    float4 v = *(const float4*)(X + (size_t)row*HDIM + t*4);

    float s = __fadd_rn(__fadd_rn(v.x,v.y), __fadd_rn(v.z,v.w));
#pragma unroll
    for (int o=16;o;o>>=1) s = __fadd_rn(s, __shfl_xor_sync(~0u, s, o));
    if ((t&31)==0) red[t>>5] = s;
    __syncthreads();
    if (t==0) {
        float a = __fadd_rn(__fadd_rn(red[0],red[1]), __fadd_rn(red[2],red[3]));
        float b = __fadd_rn(__fadd_rn(red[4],red[5]), __fadd_rn(red[6],red[7]));
        s_mu = __fadd_rn(a,b) * (1.0f/HDIM);
    }
    __syncthreads();
    const float mu = s_mu;

    float dx=__fadd_rn(v.x,-mu), dy=__fadd_rn(v.y,-mu),
          dz=__fadd_rn(v.z,-mu), dw=__fadd_rn(v.w,-mu);
    float sq = __fadd_rn(__fadd_rn(__fmul_rn(dx,dx),__fmul_rn(dy,dy)),
                         __fadd_rn(__fmul_rn(dz,dz),__fmul_rn(dw,dw)));
#pragma unroll
    for (int o=16;o;o>>=1) sq = __fadd_rn(sq, __shfl_xor_sync(~0u, sq, o));
    if ((t&31)==0) red[t>>5] = sq;
    __syncthreads();
    if (t==0) {
        float a = __fadd_rn(__fadd_rn(red[0],red[1]), __fadd_rn(red[2],red[3]));
        float b = __fadd_rn(__fadd_rn(red[4],red[5]), __fadd_rn(red[6],red[7]));
        s_rs = rsqrtf(__fadd_rn(a,b)*(1.0f/HDIM) + 1e-5f);
    }
    __syncthreads();
    const float rs = s_rs;

    float4 g4 = *(const float4*)(gam + t*4);
    float4 b4 = *(const float4*)(bet + t*4);
    float4 o;
    o.x = fmaxf(__fadd_rn(__fmul_rn(__fmul_rn(dx,rs),g4.x), b4.x), 0.f);
    o.y = fmaxf(__fadd_rn(__fmul_rn(__fmul_rn(dy,rs),g4.y), b4.y), 0.f);
    o.z = fmaxf(__fadd_rn(__fmul_rn(__fmul_rn(dz,rs),g4.z), b4.z), 0.f);
    o.w = fmaxf(__fadd_rn(__fmul_rn(__fmul_rn(dw,rs),g4.w), b4.w), 0.f);
    *(float4*)(Y + (size_t)row*HDIM + t*4) = o;
}

// ---------------- |z|^2 per VQ row (warp per row) ----------------
__global__ void znorm_k(const float* __restrict__ z, float* __restrict__ zn)
{
    int row  = blockIdx.x*8 + (threadIdx.x >> 5);
    int lane = threadIdx.x & 31;
    float4 v = *(const float4*)(z + (size_t)row*DDIM + lane*4);
    float s = __fadd_rn(__fadd_rn(__fmul_rn(v.x,v.x), __fmul_rn(v.y,v.y)),
                        __fadd_rn(__fmul_rn(v.z,v.z), __fmul_rn(v.w,v.w)));
#pragma unroll
    for (int o=16;o;o>>=1) s = __fadd_rn(s, __shfl_xor_sync(~0u, s, o));
    if (lane == 0) zn[row] = s;
}

// ---------------- codebook prep: |c_k|^2 (double acc) and transpose ----------------
__global__ void prep_k(const float* __restrict__ cb, float* __restrict__ cn,
                       float* __restrict__ cbT)
{
    int k = threadIdx.x;       // 256 threads, 1 block
    double s = 0.0;
    for (int d0=0; d0<DDIM; d0++) {
        float v = cb[k*DDIM + d0];
        s += (double)v * (double)v;
        cbT[d0*KCODES + k] = v;
    }
    cn[k] = (float)s;
}

__global__ void init_k(float* loss, int* hist)
{
    int t = threadIdx.x;
    if (t == 0) *loss = 0.f;
    if (t < KCODES) hist[t] = 0;
}

// ---------------- argmin per row (warp per row, first-min tie-break) ----------------
__global__ void argmin_k(const float* __restrict__ S, int* __restrict__ idx,
                         float* __restrict__ idx_f)
{
    int row  = blockIdx.x*8 + (threadIdx.x >> 5);
    int lane = threadIdx.x & 31;
    const float* sr = S + (size_t)row*KCODES;
    float bv = 3.4e38f; int bk = 0;
#pragma unroll
    for (int j=0;j<8;j++) {
        int k = lane + j*32;
        float v = sr[k];
        if (v < bv) { bv = v; bk = k; }
    }
#pragma unroll
    for (int o=16;o;o>>=1) {
        float ov = __shfl_xor_sync(~0u, bv, o);
        int   ok = __shfl_xor_sync(~0u, bk, o);
        if (ov < bv || (ov == bv && ok < bk)) { bv = ov; bk = ok; }
    }
    if (lane == 0) { idx[row] = bk; idx_f[row] = (float)bk; }
}

// ------ gather z_q, straight-through zq_st = fl(z + fl(zq - z)), loss, hist ------
__global__ void gather_k(const float* __restrict__ z, const float* __restrict__ cb,
                         const int* __restrict__ idx, float* __restrict__ zq,
                         float* __restrict__ loss, int* __restrict__ hist)
{
    int b = blockIdx.x;
    int t = threadIdx.x;   // 256
    __shared__ int   sidx[GG];
    __shared__ float red[8];
    if (t < GG) {
        int k = idx[b*GG + t];
        sidx[t] = k;
        atomicAdd(&hist[k], 1);
    }
    __syncthreads();
    int g = (t*4) >> 7;
    int e = (t*4) & 127;
    float4 c  = *(const float4*)(cb + (size_t)sidx[g]*DDIM + e);
    float4 zz = *(const float4*)(z  + (size_t)b*GD + t*4);
    float dx=__fadd_rn(c.x,-zz.x), dy=__fadd_rn(c.y,-zz.y),
          dz=__fadd_rn(c.z,-zz.z), dw=__fadd_rn(c.w,-zz.w);
    float4 st;
    st.x = __fadd_rn(zz.x, dx);
    st.y = __fadd_rn(zz.y, dy);
    st.z = __fadd_rn(zz.z, dz);
    st.w = __fadd_rn(zz.w, dw);
    *(float4*)(zq + (size_t)b*GD + t*4) = st;
    float s = dx*dx+dy*dy+dz*dz+dw*dw;
#pragma unroll
    for (int o=16;o;o>>=1) s += __shfl_xor_sync(~0u, s, o);
    if ((t&31)==0) red[t>>5] = s;
    __syncthreads();
    if (t==0) {
        float tot=0.f;
#pragma unroll
        for (int i=0;i<8;i++) tot += red[i];
        atomicAdd(loss, tot);
    }
}

// ---------------- finalize scalars ----------------
__global__ void finalize_k(const int* __restrict__ hist, const float* __restrict__ loss,
                           float* __restrict__ out)
{
    int t = threadIdx.x;   // 256
    __shared__ float red[8];
    float e = (float)hist[t] / (float)BG;
    float s = e * logf(e + 1e-10f);
#pragma unroll
    for (int o=16;o;o>>=1) s += __shfl_xor_sync(~0u, s, o);
    if ((t&31)==0) red[t>>5] = s;
    __syncthreads();
    if (t==0) {
        float tot=0.f;
#pragma unroll
        for (int i=0;i<8;i++) tot += red[i];
        out[PERP_OFF] = expf(-tot);
        out[0] = 1.25f * loss[0] / 33554432.0f;   // (1+BETA)*mean over B*G*D
    }
}

// ---------------- host launcher ----------------
extern "C" void kernel_launch(void* const* d_in, const int* in_sizes, int n_in,
                              void* d_out, int out_size)
{
    const float* x      = (const float*)d_in[0];
    const float* enc_w1 = (const float*)d_in[1];
    const float* enc_b1 = (const float*)d_in[2];
    const float* enc_w2 = (const float*)d_in[3];
    const float* enc_b2 = (const float*)d_in[4];
    const float* ln_g   = (const float*)d_in[5];
    const float* ln_b   = (const float*)d_in[6];
    const float* enc_w3 = (const float*)d_in[7];
    const float* enc_b3 = (const float*)d_in[8];
    const float* enc_w4 = (const float*)d_in[9];
    const float* enc_b4 = (const float*)d_in[10];
    const float* cb     = (const float*)d_in[11];
    const float* dec_w1 = (const float*)d_in[12];
    const float* dec_b1 = (const float*)d_in[13];
    const float* dec_w2 = (const float*)d_in[14];
    const float* dec_b2 = (const float*)d_in[15];
    const float* dec_w3 = (const float*)d_in[16];
    const float* dec_b3 = (const float*)d_in[17];
    float* out = (float*)d_out;

    static float *p_h1=nullptr,*p_t2,*p_h2,*p_z,*p_S,*p_zq,*p_zn,*p_cn,*p_cbT,*p_loss;
    static int *p_idx,*p_hist;
    if (!p_h1) {
        cudaGetSymbolAddress((void**)&p_h1,  g_h1);
        cudaGetSymbolAddress((void**)&p_t2,  g_t2);
        cudaGetSymbolAddress((void**)&p_h2,  g_h2);
        cudaGetSymbolAddress((void**)&p_z,   g_z);
        cudaGetSymbolAddress((void**)&p_S,   g_S);
        cudaGetSymbolAddress((void**)&p_zq,  g_zq);
        cudaGetSymbolAddress((void**)&p_zn,  g_zn);
        cudaGetSymbolAddress((void**)&p_cn,  g_cn);
        cudaGetSymbolAddress((void**)&p_cbT, g_cbT);
        cudaGetSymbolAddress((void**)&p_loss,g_loss);
        cudaGetSymbolAddress((void**)&p_idx, g_idx);
        cudaGetSymbolAddress((void**)&p_hist,g_hist);
    }

    prep_k<<<1,256>>>(cb, p_cn, p_cbT);
    init_k<<<1,256>>>(p_loss, p_hist);

    // ---- encoder (fp32, FFMA2, row-pair + dup-B fragments) ----
    gemm2_k<128,128,32,8,8,1,1><<<dim3(HDIM/128, B_SZ/128), 256>>>(x,    enc_w1, enc_b1, p_h1, B_SZ, HDIM, STATE_NN);
    gemm2_k<128,128,32,8,8,0,1><<<dim3(HDIM/128, B_SZ/128), 256>>>(p_h1, enc_w2, enc_b2, p_t2, B_SZ, HDIM, HDIM);
    ln_relu_k<<<B_SZ,256>>>(p_t2, ln_g, ln_b, p_h2);
    gemm2_k<128,128,32,8,8,1,1><<<dim3(HDIM/128, B_SZ/128), 256>>>(p_h2, enc_w3, enc_b3, p_h1, B_SZ, HDIM, HDIM);
    gemm2_k<128,128,32,8,8,0,1><<<dim3(DDIM/128, BG/128),   256>>>(p_h1, enc_w4, enc_b4, p_z,  BG,   DDIM, DDIM);

    // ---- VQ: S on the reference rounding grid (R4-exact), argmin ----
    znorm_k<<<BG/8,256>>>(p_z, p_zn);
    gemm_vq2_k<128,64,16,8,4><<<dim3(KCODES/64, BG/128), 256>>>(p_z, p_cbT, p_cn, p_zn, p_S, BG, KCODES, DDIM);
    argmin_k<<<BG/8,256>>>(p_S, p_idx, out + IDX_OFF);
    gather_k<<<B_SZ,256>>>(p_z, cb, p_idx, p_zq, p_loss, p_hist);
    finalize_k<<<1,256>>>(p_hist, p_loss, out);

    // ---- decoder (fp32, FFMA2, row-pair + dup-B fragments) ----
    gemm2_k<128,128,32,8,8,1,1><<<dim3(HDIM/128, B_SZ/128), 256>>>(p_zq, dec_w1, dec_b1, p_h2, B_SZ, HDIM, HDIM);
    gemm2_k<128,128,32,8,8,1,1><<<dim3(HDIM/128, B_SZ/128), 256>>>(p_h2, dec_w2, dec_b2, p_t2, B_SZ, HDIM, HDIM);
    gemm2_k<128, 64,32,8,4,0,0><<<dim3(1,        B_SZ/128), 256>>>(p_t2, dec_w3, dec_b3, out + DEC_OFF, B_SZ, STATE_NN, HDIM);
}

// round 8
// speedup vs baseline: 1.6947x; 1.6947x over previous
#include <cuda_runtime.h>
#include <cstdint>
#include <cmath>

#define B_SZ    32768
#define STATE_NN 64
#define HDIM    1024
#define KCODES  256
#define DDIM    128
#define GG      8
#define BG      (B_SZ*GG)      /* 262144 */
#define GD      (GG*DDIM)      /* 1024   */

#define DEC_OFF  1
#define PERP_OFF (1 + B_SZ*STATE_NN)       /* 2097153 */
#define IDX_OFF  (2 + B_SZ*STATE_NN)       /* 2097154 */

typedef unsigned long long u64;

// ---------------- device scratch (no allocations allowed) ----------------
__device__ float g_h1[(size_t)B_SZ*HDIM];
__device__ float g_t2[(size_t)B_SZ*HDIM];
__device__ float g_h2[(size_t)B_SZ*HDIM];
__device__ float g_z [(size_t)B_SZ*GD];
__device__ float g_S [(size_t)BG*KCODES];
__device__ float g_zq[(size_t)B_SZ*GD];
__device__ float g_zn[BG];
__device__ int   g_idx[BG];
__device__ int   g_hist[KCODES];
__device__ float g_cn[KCODES];
__device__ float g_cbT[DDIM*KCODES];
__device__ float g_loss[1];

// ---------------- packed f32x2 helpers ----------------
__device__ __forceinline__ u64 pack2(float lo, float hi){
    u64 r; asm("mov.b64 %0, {%1,%2};" : "=l"(r) : "f"(lo), "f"(hi)); return r;
}
__device__ __forceinline__ void unpack2(u64 v, float &lo, float &hi){
    asm("mov.b64 {%0,%1}, %2;" : "=f"(lo), "=f"(hi) : "l"(v));
}
__device__ __forceinline__ u64 ffma2(u64 a, u64 b, u64 c){
    u64 d; asm("fma.rn.f32x2 %0, %1, %2, %3;" : "=l"(d) : "l"(a), "l"(b), "l"(c)); return d;
}
__device__ __forceinline__ u64 fmul2(u64 a, u64 b){
    u64 d; asm("mul.rn.f32x2 %0, %1, %2;" : "=l"(d) : "l"(a), "l"(b)); return d;
}
__device__ __forceinline__ u64 fadd2(u64 a, u64 b){
    u64 d; asm("add.rn.f32x2 %0, %1, %2;" : "=l"(d) : "l"(a), "l"(b)); return d;
}

// =====================================================================
// fp32 GEMM, FFMA2, R6 fragment layout + 2-stage smem double buffering.
// Arithmetic (per-element k-order) identical to the R6 kernel.
// C = act( A[M,K] @ B[K,N] + bias );  ACT: 0 none, 1 relu.  VEC: float4 stores.
// =====================================================================
template<int BM,int BN,int BK,int TM,int TN,int ACT,int VEC>
__global__ void __launch_bounds__(256,2)
gemm2_k(const float* __restrict__ A, const float* __restrict__ Bm,
        const float* __restrict__ bias, float* __restrict__ C,
        int M, int N, int K)
{
    constexpr int MG = TM/4;                // A row groups
    constexpr int NG = TN/4;                // B col groups
    constexpr int ASTEP = (256/BM)*4;       // k-stride per thread for A loads
    constexpr int ANUM  = BK/ASTEP;         // float4 A loads per tile
    constexpr int BNUM  = (BK*BN)/(256*4);  // float4 B loads per tile

    __shared__ float As[2][BK][BM];         // transposed A tiles
    __shared__ float Bs[2][BK][BN];

    const int tid  = threadIdx.x;
    const int tcol = tid % (BN/TN);
    const int trow = tid / (BN/TN);
    const int aRow0 = blockIdx.y * BM;
    const int bCol0 = blockIdx.x * BN;

    // conflict-free A loader: thread owns row lr, k-offsets ls*4 + i*ASTEP
    const int lr = tid % BM;
    const int ls = tid / BM;

    u64 acc[TM][TN/2];
#pragma unroll
    for (int i=0;i<TM;i++)
#pragma unroll
        for (int j=0;j<TN/2;j++) acc[i][j] = 0ULL;

    // ---- prologue: tile 0 -> stage 0 ----
#pragma unroll
    for (int i=0;i<ANUM;i++) {
        int c0 = ls*4 + i*ASTEP;
        float4 v = *(const float4*)(A + (size_t)(aRow0+lr)*K + c0);
        As[0][c0+0][lr]=v.x; As[0][c0+1][lr]=v.y;
        As[0][c0+2][lr]=v.z; As[0][c0+3][lr]=v.w;
    }
#pragma unroll
    for (int it=0; it<BNUM; ++it) {
        int idx4 = (tid + it*256)*4;
        int r = idx4 / BN, c = idx4 % BN;
        *(float4*)&Bs[0][r][c] = *(const float4*)(Bm + (size_t)r*N + bCol0 + c);
    }
    __syncthreads();

    const int NIT = K/BK;
    for (int itk=0; itk<NIT; ++itk) {
        const int cur = itk & 1, nxt = cur ^ 1;
        const int k1 = (itk+1)*BK;
        float4 avp[ANUM], bvp[BNUM];
        if (itk+1 < NIT) {
#pragma unroll
            for (int i=0;i<ANUM;i++) {
                int c0 = ls*4 + i*ASTEP;
                avp[i] = *(const float4*)(A + (size_t)(aRow0+lr)*K + k1 + c0);
            }
#pragma unroll
            for (int it=0; it<BNUM; ++it) {
                int idx4 = (tid + it*256)*4;
                int r = idx4 / BN, c = idx4 % BN;
                bvp[it] = *(const float4*)(Bm + (size_t)(k1+r)*N + bCol0 + c);
            }
        }
        // ---- compute stage cur (R6-identical inner loop) ----
#pragma unroll
        for (int kk=0; kk<BK; kk++) {
            u64 ar2[TM], br2[TN/2];
#pragma unroll
            for (int h=0; h<MG; h++) {
                float4 av = *(const float4*)&As[cur][kk][h*(BM/2) + trow*4];
                ar2[h*4+0] = pack2(av.x, av.x);
                ar2[h*4+1] = pack2(av.y, av.y);
                ar2[h*4+2] = pack2(av.z, av.z);
                ar2[h*4+3] = pack2(av.w, av.w);
            }
#pragma unroll
            for (int g=0; g<NG; g++) {
                ulonglong2 bv = *(const ulonglong2*)&Bs[cur][kk][g*(BN/2) + tcol*4];
                br2[g*2+0] = bv.x;
                br2[g*2+1] = bv.y;
            }
#pragma unroll
            for (int i=0;i<TM;i++)
#pragma unroll
                for (int j=0;j<TN/2;j++)
                    acc[i][j] = ffma2(ar2[i], br2[j], acc[i][j]);
        }
        // ---- stage next tile ----
        if (itk+1 < NIT) {
#pragma unroll
            for (int i=0;i<ANUM;i++) {
                int c0 = ls*4 + i*ASTEP;
                As[nxt][c0+0][lr]=avp[i].x; As[nxt][c0+1][lr]=avp[i].y;
                As[nxt][c0+2][lr]=avp[i].z; As[nxt][c0+3][lr]=avp[i].w;
            }
#pragma unroll
            for (int it=0; it<BNUM; ++it) {
                int idx4 = (tid + it*256)*4;
                int r = idx4 / BN, c = idx4 % BN;
                *(float4*)&Bs[nxt][r][c] = bvp[it];
            }
        }
        __syncthreads();
    }

    // ---- epilogue (R6-identical) ----
#pragma unroll
    for (int h=0; h<MG; h++) {
#pragma unroll
        for (int i=0;i<4;i++) {
            size_t r = (size_t)aRow0 + h*(BM/2) + trow*4 + i;
#pragma unroll
            for (int g=0; g<NG; g++) {
                int c0 = bCol0 + g*(BN/2) + tcol*4;
                float v0,v1,v2,v3;
                unpack2(acc[h*4+i][g*2+0], v0, v1);
                unpack2(acc[h*4+i][g*2+1], v2, v3);
                v0 += bias[c0+0]; v1 += bias[c0+1];
                v2 += bias[c0+2]; v3 += bias[c0+3];
                if (ACT == 1) {
                    v0 = fmaxf(v0,0.f); v1 = fmaxf(v1,0.f);
                    v2 = fmaxf(v2,0.f); v3 = fmaxf(v3,0.f);
                }
                if (VEC) {
                    float4 o; o.x=v0; o.y=v1; o.z=v2; o.w=v3;
                    *(float4*)(C + r*N + c0) = o;
                } else {
                    C[r*N + c0+0]=v0; C[r*N + c0+1]=v1;
                    C[r*N + c0+2]=v2; C[r*N + c0+3]=v3;
                }
            }
        }
    }
}

// =====================================================================
// VQ-score GEMM: packed Kahan dot (compute byte-identical to R4/R6),
// now with 2-stage smem double buffering (load scheduling only).
// S = fl( fl(zn[r] + cn[c]) - 2*dot ) on the reference rounding grid.
// =====================================================================
template<int BM,int BN,int BK,int TM,int TN>
__global__ void __launch_bounds__(256,2)
gemm_vq2_k(const float* __restrict__ A, const float* __restrict__ Bm,
           const float* __restrict__ cn, const float* __restrict__ zn,
           float* __restrict__ C, int M, int N, int K)
{
    constexpr int ANUM = (BM*BK)/(256*4);
    constexpr int BNUM = (BK*BN)/(256*4);
    __shared__ float As[2][BK][BM];
    __shared__ float Bs[2][BK][BN];

    const int tid  = threadIdx.x;
    const int tcol = tid % (BN/TN);
    const int trow = tid / (BN/TN);
    const int aRow0 = blockIdx.y * BM;
    const int bCol0 = blockIdx.x * BN;
    const u64 SGN = 0x8000000080000000ULL;

    u64 s[TM][TN/2], e[TM][TN/2];
#pragma unroll
    for (int i=0;i<TM;i++)
#pragma unroll
        for (int j=0;j<TN/2;j++) { s[i][j]=0ULL; e[i][j]=0ULL; }

    // ---- prologue: tile 0 -> stage 0 ----
#pragma unroll
    for (int it=0; it<ANUM; ++it) {
        int idx4 = (tid + it*256)*4;
        int r = idx4 / BK, c = idx4 % BK;
        float4 v = *(const float4*)(A + (size_t)(aRow0+r)*K + c);
        As[0][c+0][r]=v.x; As[0][c+1][r]=v.y; As[0][c+2][r]=v.z; As[0][c+3][r]=v.w;
    }
#pragma unroll
    for (int it=0; it<BNUM; ++it) {
        int idx4 = (tid + it*256)*4;
        int r = idx4 / BN, c = idx4 % BN;
        *(float4*)&Bs[0][r][c] = *(const float4*)(Bm + (size_t)r*N + bCol0 + c);
    }
    __syncthreads();

    const int NIT = K/BK;
    for (int itk=0; itk<NIT; ++itk) {
        const int cur = itk & 1, nxt = cur ^ 1;
        const int k1 = (itk+1)*BK;
        float4 avp[ANUM], bvp[BNUM];
        if (itk+1 < NIT) {
#pragma unroll
            for (int it=0; it<ANUM; ++it) {
                int idx4 = (tid + it*256)*4;
                int r = idx4 / BK, c = idx4 % BK;
                avp[it] = *(const float4*)(A + (size_t)(aRow0+r)*K + k1 + c);
            }
#pragma unroll
            for (int it=0; it<BNUM; ++it) {
                int idx4 = (tid + it*256)*4;
                int r = idx4 / BN, c = idx4 % BN;
                bvp[it] = *(const float4*)(Bm + (size_t)(k1+r)*N + bCol0 + c);
            }
        }
        // ---- compute stage cur (R4/R6-identical Kahan sequence) ----
#pragma unroll
        for (int kk=0; kk<BK; kk++) {
            u64 ar2[TM], br2[TN/2];
#pragma unroll
            for (int i=0;i<TM;i++) {
                float a = As[cur][kk][trow*TM+i];
                ar2[i] = pack2(a, a);
            }
            {
                ulonglong2 b2 = *(const ulonglong2*)&Bs[cur][kk][tcol*TN];
                br2[0] = b2.x;
                br2[1] = b2.y;
            }
#pragma unroll
            for (int i=0;i<TM;i++)
#pragma unroll
                for (int j=0;j<TN/2;j++) {
                    u64 x  = fmul2(ar2[i], br2[j]);
                    u64 t  = fadd2(s[i][j], x);
                    u64 c1 = fadd2(fadd2(s[i][j], t ^ SGN), x);  // (s-t)+x
                    e[i][j] = fadd2(e[i][j], c1);
                    s[i][j] = t;
                }
        }
        // ---- stage next tile ----
        if (itk+1 < NIT) {
#pragma unroll
            for (int it=0; it<ANUM; ++it) {
                int idx4 = (tid + it*256)*4;
                int r = idx4 / BK, c = idx4 % BK;
                As[nxt][c+0][r]=avp[it].x; As[nxt][c+1][r]=avp[it].y;
                As[nxt][c+2][r]=avp[it].z; As[nxt][c+3][r]=avp[it].w;
            }
#pragma unroll
            for (int it=0; it<BNUM; ++it) {
                int idx4 = (tid + it*256)*4;
                int r = idx4 / BN, c = idx4 % BN;
                *(float4*)&Bs[nxt][r][c] = bvp[it];
            }
        }
        __syncthreads();
    }
#pragma unroll
    for (int i=0;i<TM;i++) {
        size_t r = (size_t)aRow0 + trow*TM + i;
        float zr = zn[r];
#pragma unroll
        for (int j=0;j<TN/2;j++) {
            int c = bCol0 + tcol*TN + 2*j;
            float s0,s1,e0,e1;
            unpack2(s[i][j], s0, s1);
            unpack2(e[i][j], e0, e1);
            float dot0 = __fadd_rn(s0, e0);
            float dot1 = __fadd_rn(s1, e1);
            float t0 = __fadd_rn(zr, cn[c]);
            float t1 = __fadd_rn(zr, cn[c+1]);
            C[r*N + c]   = __fadd_rn(t0, __fmul_rn(-2.f, dot0));
            C[r*N + c+1] = __fadd_rn(t1, __fmul_rn(-2.f, dot1));
        }
    }
}

// ---------------- LayerNorm + ReLU (row of 1024, 256 threads) ----------------
__global__ void ln_relu_k(const float* __restrict__ X, const float* __restrict__ gam,
                          const float* __restrict__ bet, float* __restrict__ Y)
{
    const int row = blockIdx.x;
    const int t   = threadIdx.x;
    __shared__ float red[8];
    __shared__ float s_mu, s_rs;

    float4 v = *(const float4*)(X + (size_t)row*HDIM + t*4);

    float s = __fadd_rn(__fadd_rn(v.x,v.y), __fadd_rn(v.z,v.w));
#pragma unroll
    for (int o=16;o;o>>=1) s = __fadd_rn(s, __shfl_xor_sync(~0u, s, o));
    if ((t&31)==0) red[t>>5] = s;
    __syncthreads();
    if (t==0) {
        float a = __fadd_rn(__fadd_rn(red[0],red[1]), __fadd_rn(red[2],red[3]));
        float b = __fadd_rn(__fadd_rn(red[4],red[5]), __fadd_rn(red[6],red[7]));
        s_mu = __fadd_rn(a,b) * (1.0f/HDIM);
    }
    __syncthreads();
    const float mu = s_mu;

    float dx=__fadd_rn(v.x,-mu), dy=__fadd_rn(v.y,-mu),
          dz=__fadd_rn(v.z,-mu), dw=__fadd_rn(v.w,-mu);
    float sq = __fadd_rn(__fadd_rn(__fmul_rn(dx,dx),__fmul_rn(dy,dy)),
                         __fadd_rn(__fmul_rn(dz,dz),__fmul_rn(dw,dw)));
#pragma unroll
    for (int o=16;o;o>>=1) sq = __fadd_rn(sq, __shfl_xor_sync(~0u, sq, o));
    if ((t&31)==0) red[t>>5] = sq;
    __syncthreads();
    if (t==0) {
        float a = __fadd_rn(__fadd_rn(red[0],red[1]), __fadd_rn(red[2],red[3]));
        float b = __fadd_rn(__fadd_rn(red[4],red[5]), __fadd_rn(red[6],red[7]));
        s_rs = rsqrtf(__fadd_rn(a,b)*(1.0f/HDIM) + 1e-5f);
    }
    __syncthreads();
    const float rs = s_rs;

    float4 g4 = *(const float4*)(gam + t*4);
    float4 b4 = *(const float4*)(bet + t*4);
    float4 o;
    o.x = fmaxf(__fadd_rn(__fmul_rn(__fmul_rn(dx,rs),g4.x), b4.x), 0.f);
    o.y = fmaxf(__fadd_rn(__fmul_rn(__fmul_rn(dy,rs),g4.y), b4.y), 0.f);
    o.z = fmaxf(__fadd_rn(__fmul_rn(__fmul_rn(dz,rs),g4.z), b4.z), 0.f);
    o.w = fmaxf(__fadd_rn(__fmul_rn(__fmul_rn(dw,rs),g4.w), b4.w), 0.f);
    *(float4*)(Y + (size_t)row*HDIM + t*4) = o;
}

// ---------------- |z|^2 per VQ row (warp per row) ----------------
__global__ void znorm_k(const float* __restrict__ z, float* __restrict__ zn)
{
    int row  = blockIdx.x*8 + (threadIdx.x >> 5);
    int lane = threadIdx.x & 31;
    float4 v = *(const float4*)(z + (size_t)row*DDIM + lane*4);
    float s = __fadd_rn(__fadd_rn(__fmul_rn(v.x,v.x), __fmul_rn(v.y,v.y)),
                        __fadd_rn(__fmul_rn(v.z,v.z), __fmul_rn(v.w,v.w)));
#pragma unroll
    for (int o=16;o;o>>=1) s = __fadd_rn(s, __shfl_xor_sync(~0u, s, o));
    if (lane == 0) zn[row] = s;
}

// ---------------- codebook prep: |c_k|^2 (double acc) and transpose ----------------
__global__ void prep_k(const float* __restrict__ cb, float* __restrict__ cn,
                       float* __restrict__ cbT)
{
    int k = threadIdx.x;       // 256 threads, 1 block
    double s = 0.0;
    for (int d0=0; d0<DDIM; d0++) {
        float v = cb[k*DDIM + d0];
        s += (double)v * (double)v;
        cbT[d0*KCODES + k] = v;
    }
    cn[k] = (float)s;
}

__global__ void init_k(float* loss, int* hist)
{
    int t = threadIdx.x;
    if (t == 0) *loss = 0.f;
    if (t < KCODES) hist[t] = 0;
}

// ---------------- argmin per row (warp per row, first-min tie-break) ----------------
__global__ void argmin_k(const float* __restrict__ S, int* __restrict__ idx,
                         float* __restrict__ idx_f)
{
    int row  = blockIdx.x*8 + (threadIdx.x >> 5);
    int lane = threadIdx.x & 31;
    const float* sr = S + (size_t)row*KCODES;
    float bv = 3.4e38f; int bk = 0;
#pragma unroll
    for (int j=0;j<8;j++) {
        int k = lane + j*32;
        float v = sr[k];
        if (v < bv) { bv = v; bk = k; }
    }
#pragma unroll
    for (int o=16;o;o>>=1) {
        float ov = __shfl_xor_sync(~0u, bv, o);
        int   ok = __shfl_xor_sync(~0u, bk, o);
        if (ov < bv || (ov == bv && ok < bk)) { bv = ov; bk = ok; }
    }
    if (lane == 0) { idx[row] = bk; idx_f[row] = (float)bk; }
}

// ------ gather z_q, straight-through zq_st = fl(z + fl(zq - z)), loss, hist ------
__global__ void gather_k(const float* __restrict__ z, const float* __restrict__ cb,
                         const int* __restrict__ idx, float* __restrict__ zq,
                         float* __restrict__ loss, int* __restrict__ hist)
{
    int b = blockIdx.x;
    int t = threadIdx.x;   // 256
    __shared__ int   sidx[GG];
    __shared__ float red[8];
    if (t < GG) {
        int k = idx[b*GG + t];
        sidx[t] = k;
        atomicAdd(&hist[k], 1);
    }
    __syncthreads();
    int g = (t*4) >> 7;
    int e = (t*4) & 127;
    float4 c  = *(const float4*)(cb + (size_t)sidx[g]*DDIM + e);
    float4 zz = *(const float4*)(z  + (size_t)b*GD + t*4);
    float dx=__fadd_rn(c.x,-zz.x), dy=__fadd_rn(c.y,-zz.y),
          dz=__fadd_rn(c.z,-zz.z), dw=__fadd_rn(c.w,-zz.w);
    float4 st;
    st.x = __fadd_rn(zz.x, dx);
    st.y = __fadd_rn(zz.y, dy);
    st.z = __fadd_rn(zz.z, dz);
    st.w = __fadd_rn(zz.w, dw);
    *(float4*)(zq + (size_t)b*GD + t*4) = st;
    float s = dx*dx+dy*dy+dz*dz+dw*dw;
#pragma unroll
    for (int o=16;o;o>>=1) s += __shfl_xor_sync(~0u, s, o);
    if ((t&31)==0) red[t>>5] = s;
    __syncthreads();
    if (t==0) {
        float tot=0.f;
#pragma unroll
        for (int i=0;i<8;i++) tot += red[i];
        atomicAdd(loss, tot);
    }
}

// ---------------- finalize scalars ----------------
__global__ void finalize_k(const int* __restrict__ hist, const float* __restrict__ loss,
                           float* __restrict__ out)
{
    int t = threadIdx.x;   // 256
    __shared__ float red[8];
    float e = (float)hist[t] / (float)BG;
    float s = e * logf(e + 1e-10f);
#pragma unroll
    for (int o=16;o;o>>=1) s += __shfl_xor_sync(~0u, s, o);
    if ((t&31)==0) red[t>>5] = s;
    __syncthreads();
    if (t==0) {
        float tot=0.f;
#pragma unroll
        for (int i=0;i<8;i++) tot += red[i];
        out[PERP_OFF] = expf(-tot);
        out[0] = 1.25f * loss[0] / 33554432.0f;   // (1+BETA)*mean over B*G*D
    }
}

// ---------------- host launcher ----------------
extern "C" void kernel_launch(void* const* d_in, const int* in_sizes, int n_in,
                              void* d_out, int out_size)
{
    const float* x      = (const float*)d_in[0];
    const float* enc_w1 = (const float*)d_in[1];
    const float* enc_b1 = (const float*)d_in[2];
    const float* enc_w2 = (const float*)d_in[3];
    const float* enc_b2 = (const float*)d_in[4];
    const float* ln_g   = (const float*)d_in[5];
    const float* ln_b   = (const float*)d_in[6];
    const float* enc_w3 = (const float*)d_in[7];
    const float* enc_b3 = (const float*)d_in[8];
    const float* enc_w4 = (const float*)d_in[9];
    const float* enc_b4 = (const float*)d_in[10];
    const float* cb     = (const float*)d_in[11];
    const float* dec_w1 = (const float*)d_in[12];
    const float* dec_b1 = (const float*)d_in[13];
    const float* dec_w2 = (const float*)d_in[14];
    const float* dec_b2 = (const float*)d_in[15];
    const float* dec_w3 = (const float*)d_in[16];
    const float* dec_b3 = (const float*)d_in[17];
    float* out = (float*)d_out;

    static float *p_h1=nullptr,*p_t2,*p_h2,*p_z,*p_S,*p_zq,*p_zn,*p_cn,*p_cbT,*p_loss;
    static int *p_idx,*p_hist;
    if (!p_h1) {
        cudaGetSymbolAddress((void**)&p_h1,  g_h1);
        cudaGetSymbolAddress((void**)&p_t2,  g_t2);
        cudaGetSymbolAddress((void**)&p_h2,  g_h2);
        cudaGetSymbolAddress((void**)&p_z,   g_z);
        cudaGetSymbolAddress((void**)&p_S,   g_S);
        cudaGetSymbolAddress((void**)&p_zq,  g_zq);
        cudaGetSymbolAddress((void**)&p_zn,  g_zn);
        cudaGetSymbolAddress((void**)&p_cn,  g_cn);
        cudaGetSymbolAddress((void**)&p_cbT, g_cbT);
        cudaGetSymbolAddress((void**)&p_loss,g_loss);
        cudaGetSymbolAddress((void**)&p_idx, g_idx);
        cudaGetSymbolAddress((void**)&p_hist,g_hist);
    }

    prep_k<<<1,256>>>(cb, p_cn, p_cbT);
    init_k<<<1,256>>>(p_loss, p_hist);

    // ---- encoder (fp32, FFMA2, dbuf) ----
    gemm2_k<128,128,16,8,8,1,1><<<dim3(HDIM/128, B_SZ/128), 256>>>(x,    enc_w1, enc_b1, p_h1, B_SZ, HDIM, STATE_NN);
    gemm2_k<128,128,16,8,8,0,1><<<dim3(HDIM/128, B_SZ/128), 256>>>(p_h1, enc_w2, enc_b2, p_t2, B_SZ, HDIM, HDIM);
    ln_relu_k<<<B_SZ,256>>>(p_t2, ln_g, ln_b, p_h2);
    gemm2_k<128,128,16,8,8,1,1><<<dim3(HDIM/128, B_SZ/128), 256>>>(p_h2, enc_w3, enc_b3, p_h1, B_SZ, HDIM, HDIM);
    gemm2_k<128,128,16,8,8,0,1><<<dim3(DDIM/128, BG/128),   256>>>(p_h1, enc_w4, enc_b4, p_z,  BG,   DDIM, DDIM);

    // ---- VQ: S on the reference rounding grid (R4-exact compute), argmin ----
    znorm_k<<<BG/8,256>>>(p_z, p_zn);
    gemm_vq2_k<128,64,16,8,4><<<dim3(KCODES/64, BG/128), 256>>>(p_z, p_cbT, p_cn, p_zn, p_S, BG, KCODES, DDIM);
    argmin_k<<<BG/8,256>>>(p_S, p_idx, out + IDX_OFF);
    gather_k<<<B_SZ,256>>>(p_z, cb, p_idx, p_zq, p_loss, p_hist);
    finalize_k<<<1,256>>>(p_hist, p_loss, out);

    // ---- decoder (fp32, FFMA2, dbuf) ----
    gemm2_k<128,128,16,8,8,1,1><<<dim3(HDIM/128, B_SZ/128), 256>>>(p_zq, dec_w1, dec_b1, p_h2, B_SZ, HDIM, HDIM);
    gemm2_k<128,128,16,8,8,1,1><<<dim3(HDIM/128, B_SZ/128), 256>>>(p_h2, dec_w2, dec_b2, p_t2, B_SZ, HDIM, HDIM);
    gemm2_k<128, 64,16,8,4,0,0><<<dim3(1,        B_SZ/128), 256>>>(p_t2, dec_w3, dec_b3, out + DEC_OFF, B_SZ, STATE_NN, HDIM);
}